// round 14
// baseline (speedup 1.0000x reference)
#include <cuda_runtime.h>
#include <cstdint>

#define LN_EPS 1e-5f
#define EPS_ATTN 1e-8f
#define SCALE 0.08838834764831845f
typedef unsigned long long ull;

__device__ __forceinline__ ull fma2(ull a, ull b, ull c){ ull d; asm("fma.rn.f32x2 %0,%1,%2,%3;":"=l"(d):"l"(a),"l"(b),"l"(c)); return d; }
__device__ __forceinline__ ull add2(ull a, ull b){ ull d; asm("add.rn.f32x2 %0,%1,%2;":"=l"(d):"l"(a),"l"(b)); return d; }
__device__ __forceinline__ ull pk2(float lo, float hi){ ull d; asm("mov.b64 %0,{%1,%2};":"=l"(d):"f"(lo),"f"(hi)); return d; }
__device__ __forceinline__ void unpk(ull v, float&lo, float&hi){ asm("mov.b64 {%0,%1},%2;":"=f"(lo),"=f"(hi):"l"(v)); }
__device__ __forceinline__ float up2(ull v){ float a,b; unpk(v,a,b); return a+b; }

__device__ float g_slots_n[131072];
__device__ float g_qk[131072];
__device__ float g_qksum[1024];
__device__ float g_part[8388608];   // [b][64 tiles][8 s][128]
__device__ float g_cs[65536];       // [b][tile][s]
__device__ float g_cb[65536];
// transposed weights
__device__ __align__(16) float g_WihT[49152];  // [128 d][384 j]
__device__ __align__(16) float g_WhhT[49152];
__device__ __align__(16) float g_W1T[32768];   // [128 d][256 j]
__device__ __align__(16) float g_W2T[32768];   // [256 h][128 t]
__device__ __align__(16) float g_WvT[16384];   // [128 d][128 t]
__device__ __align__(16) float g_WqT[16384];

// ---- one-time weight transposes ----
__global__ void k_transpose(const float* __restrict__ Wih, const float* __restrict__ Whh,
                            const float* __restrict__ W1, const float* __restrict__ W2,
                            const float* __restrict__ Wv, const float* __restrict__ Wq){
    int i = blockIdx.x*256 + threadIdx.x;
    if(i < 49152){ int d=i/384, j=i%384; g_WihT[i]=Wih[j*128+d]; return; }
    i -= 49152;
    if(i < 49152){ int d=i/384, j=i%384; g_WhhT[i]=Whh[j*128+d]; return; }
    i -= 49152;
    if(i < 32768){ int d=i/256, j=i%256; g_W1T[i]=W1[j*128+d]; return; }
    i -= 32768;
    if(i < 32768){ int h=i/128, tt=i%128; g_W2T[i]=W2[tt*256+h]; return; }
    i -= 32768;
    if(i < 16384){ int d=i/128, tt=i%128; g_WvT[i]=Wv[tt*128+d]; return; }
    i -= 16384;
    if(i < 16384){ int d=i/128, j=i%128; g_WqT[i]=Wq[j*128+d]; }
}

// ---- group reduction: 256 threads, 2 groups of 128 (4 warps each) ----
__device__ __forceinline__ float gsum4w(float v, int t, volatile float* red){
    #pragma unroll
    for(int o=16;o>0;o>>=1) v += __shfl_xor_sync(0xffffffffu,v,o);
    if((t&31)==0) red[t>>5]=v;
    __syncthreads();
    int base=(t>>7)<<2;
    v = red[base]+red[base+1]+red[base+2]+red[base+3];
    __syncthreads();
    return v;
}

// ---- shared projection: LN(sd) -> slots_n, q = sn@Wq.T, qk = q@Wk, qksum ----
// 256 threads: group g2=t>>7 owns slots 4*g2..+3; thread owns col c=t&127.
// Pair-interleaved smem layouts: SNP/QsP[d*8 + s].
__device__ __forceinline__ void project4(
    int b, int t, int c, int g2, const float* sd,
    float* SNP, float* QsP, volatile float* red, const float* __restrict__ Wk)
{
    int s0=4*g2;
    #pragma unroll
    for(int sl=0;sl<4;sl++){
        float m = gsum4w(sd[sl],t,red)*(1.f/128.f);
        float dv = sd[sl]-m;
        float var = gsum4w(dv*dv,t,red)*(1.f/128.f);
        float sn = dv*rsqrtf(var+LN_EPS);
        SNP[c*8+s0+sl]=sn;
        g_slots_n[(b*8+s0+sl)*128+c]=sn;
    }
    __syncthreads();
    ull q0=0ull,q1=0ull;
    #pragma unroll 8
    for(int d=0;d<128;d++){
        float w=g_WqT[d*128+c]; ull wp=pk2(w,w);
        q0=fma2(wp,*(const ull*)(SNP+d*8+s0),q0);
        q1=fma2(wp,*(const ull*)(SNP+d*8+s0+2),q1);
    }
    {
        float y0,y1,y2,y3; unpk(q0,y0,y1); unpk(q1,y2,y3);
        QsP[c*8+s0]=y0; QsP[c*8+s0+1]=y1; QsP[c*8+s0+2]=y2; QsP[c*8+s0+3]=y3;
    }
    __syncthreads();
    ull k0=0ull,k1=0ull;
    #pragma unroll 8
    for(int d=0;d<128;d++){
        float w=Wk[d*128+c]; ull wp=pk2(w,w);
        k0=fma2(wp,*(const ull*)(QsP+d*8+s0),k0);
        k1=fma2(wp,*(const ull*)(QsP+d*8+s0+2),k1);
    }
    float kk[4]; unpk(k0,kk[0],kk[1]); unpk(k1,kk[2],kk[3]);
    #pragma unroll
    for(int sl=0;sl<4;sl++){
        g_qk[(b*8+s0+sl)*128+c]=kk[sl];
        float qs=gsum4w(kk[sl],t,red);
        if(c==0) g_qksum[b*8+s0+sl]=qs;
    }
}

__global__ void __launch_bounds__(256) k_init_proj(
    const float* __restrict__ noise, const float* __restrict__ mu, const float* __restrict__ ls,
    const float* __restrict__ Wk)
{
    __shared__ __align__(16) float SNP[1024];
    __shared__ __align__(16) float QsP[1024];
    __shared__ volatile float red[8];
    int b=blockIdx.x, t=threadIdx.x, c=t&127, g2=t>>7, s0=4*g2;
    float e=expf(ls[c]), m=mu[c];
    float sd[4];
    #pragma unroll
    for(int sl=0;sl<4;sl++)
        sd[sl]=m+e*noise[(b*8+s0+sl)*128+c];
    project4(b,t,c,g2,sd,SNP,QsP,red,Wk);
}

// ---- attention: grid(64,128) tiles of 64 rows, 256 threads, 3 blocks/SM ----
#define ATTN_SMEM_BYTES 75680
__global__ void __launch_bounds__(256,3) k_attn(const float* __restrict__ inputs){
    extern __shared__ float sm[];
    float* XS  = sm;            // 64*132 = 8448
    float* QK  = sm+8448;       // 1024
    float* LG  = sm+9472;       // 64*9 = 576
    float* AA  = sm+10048;      // 512
    float* QS  = sm+10560;      // 8
    float* MUb = sm+10568;      // 64
    float* RSb = sm+10632;      // 64
    float* CW  = sm+10696;      // 16
    float* CBv = sm+10712;      // 16
    float* PART= sm+10728;      // 8*8*128 = 8192   (total 18920 floats)
    const int t=threadIdx.x, lane=t&31, w=t>>5;
    const int tile=blockIdx.x, b=blockIdx.y;
    const int row=t&63, h=t>>6, sb=2*h;

    { const float4* gsrc=(const float4*)(inputs + ((size_t)b*4096 + tile*64)*128);
      #pragma unroll 8
      for(int j=t;j<2048;j+=256){ int r=j>>5,cc=j&31; *(float4*)(XS+r*132+cc*4)=gsrc[j]; } }
    { int s=t>>5, i=lane*4;
      *(float4*)(QK+s*128+i)=*(const float4*)(g_qk+(b*8+s)*128+i);
      if(t<8) QS[t]=g_qksum[b*8+t]; }
    __syncthreads();

    // phase 2: thread (h,row) computes 2 slot dots; h==0 also computes LN stats
    float at0, at1, mu, rstd;
    {
        ull p0=0ull,p1=0ull,s1=0ull,s2=0ull;
        const ulonglong2* xp=(const ulonglong2*)(XS+row*132);
        const ulonglong2* qa=(const ulonglong2*)(QK+sb*128);
        const ulonglong2* qb=(const ulonglong2*)(QK+(sb+1)*128);
        #pragma unroll 4
        for(int cc=0;cc<32;cc++){
            ulonglong2 xv=xp[cc];
            if(h==0){ s1=add2(s1,xv.x); s1=add2(s1,xv.y);
                      s2=fma2(xv.x,xv.x,s2); s2=fma2(xv.y,xv.y,s2); }
            ulonglong2 qv=qa[cc]; p0=fma2(xv.x,qv.x,p0); p0=fma2(xv.y,qv.y,p0);
            qv=qb[cc]; p1=fma2(xv.x,qv.x,p1); p1=fma2(xv.y,qv.y,p1);
        }
        LG[row*9+sb]=up2(p0); LG[row*9+sb+1]=up2(p1);
        if(h==0){
            float sum=up2(s1), ssq=up2(s2);
            float m_=sum*(1.f/128.f);
            MUb[row]=m_;
            RSb[row]=rsqrtf(ssq*(1.f/128.f)-m_*m_+LN_EPS);
        }
    }
    __syncthreads();
    mu=MUb[row]; rstd=RSb[row];
    {
        float lg[8];
        #pragma unroll
        for(int k=0;k<8;k++) lg[k]=SCALE*rstd*(LG[row*9+k]-mu*QS[k]);
        float m=lg[0];
        #pragma unroll
        for(int k=1;k<8;k++) m=fmaxf(m,lg[k]);
        float e[8], tot=0.f;
        #pragma unroll
        for(int k=0;k<8;k++){ e[k]=__expf(lg[k]-m); tot+=e[k]; }
        float inv=1.f/tot;
        at0=e[sb]*inv+EPS_ATTN;
        at1=e[sb+1]*inv+EPS_ATTN;
        AA[row*8+sb]=at0*rstd;
        AA[row*8+sb+1]=at1*rstd;
    }
    {
        float v0=at0, v1=at1, u0=at0*rstd*mu, u1=at1*rstd*mu;
        #pragma unroll
        for(int o=16;o>0;o>>=1){
            v0+=__shfl_xor_sync(0xffffffffu,v0,o);
            v1+=__shfl_xor_sync(0xffffffffu,v1,o);
            u0+=__shfl_xor_sync(0xffffffffu,u0,o);
            u1+=__shfl_xor_sync(0xffffffffu,u1,o);
        }
        if(lane==0){ CW[w*2]=v0; CW[w*2+1]=v1; CBv[w*2]=u0; CBv[w*2+1]=u1; }
    }
    __syncthreads();

    // phase 3: warp w -> rows [w*8, w*8+8), lane -> cols lane*4..+3
    ull acc[8][2];
    #pragma unroll
    for(int s=0;s<8;s++){ acc[s][0]=0ull; acc[s][1]=0ull; }
    #pragma unroll
    for(int r0=0;r0<8;r0++){
        int r=w*8+r0;
        ulonglong2 xv=*(const ulonglong2*)(XS + r*132 + lane*4);
        const float* a8=AA+r*8;
        float4 alo=*(const float4*)a8, ahi=*(const float4*)(a8+4);
        acc[0][0]=fma2(pk2(alo.x,alo.x),xv.x,acc[0][0]); acc[0][1]=fma2(pk2(alo.x,alo.x),xv.y,acc[0][1]);
        acc[1][0]=fma2(pk2(alo.y,alo.y),xv.x,acc[1][0]); acc[1][1]=fma2(pk2(alo.y,alo.y),xv.y,acc[1][1]);
        acc[2][0]=fma2(pk2(alo.z,alo.z),xv.x,acc[2][0]); acc[2][1]=fma2(pk2(alo.z,alo.z),xv.y,acc[2][1]);
        acc[3][0]=fma2(pk2(alo.w,alo.w),xv.x,acc[3][0]); acc[3][1]=fma2(pk2(alo.w,alo.w),xv.y,acc[3][1]);
        acc[4][0]=fma2(pk2(ahi.x,ahi.x),xv.x,acc[4][0]); acc[4][1]=fma2(pk2(ahi.x,ahi.x),xv.y,acc[4][1]);
        acc[5][0]=fma2(pk2(ahi.y,ahi.y),xv.x,acc[5][0]); acc[5][1]=fma2(pk2(ahi.y,ahi.y),xv.y,acc[5][1]);
        acc[6][0]=fma2(pk2(ahi.z,ahi.z),xv.x,acc[6][0]); acc[6][1]=fma2(pk2(ahi.z,ahi.z),xv.y,acc[6][1]);
        acc[7][0]=fma2(pk2(ahi.w,ahi.w),xv.x,acc[7][0]); acc[7][1]=fma2(pk2(ahi.w,ahi.w),xv.y,acc[7][1]);
    }
    if(t<8){
        int s=t, hh=s>>1, j=s&1;
        g_cs[(b*64+tile)*8+s]=CW[(2*hh)*2+j]+CW[(2*hh+1)*2+j];
        g_cb[(b*64+tile)*8+s]=CBv[(2*hh)*2+j]+CBv[(2*hh+1)*2+j];
    }
    #pragma unroll
    for(int s=0;s<8;s++)
        *(ulonglong2*)(PART+(w*8+s)*128+lane*4)=make_ulonglong2(acc[s][0],acc[s][1]);
    __syncthreads();
    {
        int s=t>>5, c0=lane*4;
        float o0=0.f,o1=0.f,o2=0.f,o3=0.f;
        #pragma unroll
        for(int w8=0;w8<8;w8++){
            const float* pp=PART+(w8*8+s)*128+c0;
            o0+=pp[0]; o1+=pp[1]; o2+=pp[2]; o3+=pp[3];
        }
        *(float4*)(g_part+((size_t)(b*64+tile)*8+s)*128+c0)=make_float4(o0,o1,o2,o3);
    }
}

// ---- fused update + projection: 128 blocks x 256 threads, coalesced WT GEMMs ----
__global__ void __launch_bounds__(256) k_update(
    const float* __restrict__ Wk,
    const float* __restrict__ b_ih, const float* __restrict__ b_hh,
    const float* __restrict__ b1, const float* __restrict__ b2,
    float* __restrict__ out, int last)
{
    __shared__ __align__(16) float TsP[1024];
    __shared__ __align__(16) float UsP[1024];
    __shared__ __align__(16) float HsP[1024];
    __shared__ __align__(16) float LNP[1024];
    __shared__ __align__(16) float QsP[1024];
    __shared__ __align__(16) float H1P[2048];
    __shared__ float CSs[8], CBs[8];
    __shared__ volatile float red[8];
    int b=blockIdx.x, t=threadIdx.x, c=t&127, g2=t>>7, s0=4*g2;

    if(t<8){
        float cs=0.f,cb=0.f;
        #pragma unroll 8
        for(int k=0;k<64;k++){ cs+=g_cs[(b*64+k)*8+t]; cb+=g_cb[(b*64+k)*8+t]; }
        CSs[t]=1.f/cs; CBs[t]=cb;
    }
    float a[4]={0.f,0.f,0.f,0.f};
    {
        const float* p=g_part+(size_t)(b*64)*1024 + s0*128 + c;
        #pragma unroll 4
        for(int k=0;k<64;k++){
            #pragma unroll
            for(int sl=0;sl<4;sl++) a[sl]+=p[(size_t)k*1024 + sl*128];
        }
    }
    float hv[4];
    #pragma unroll
    for(int sl=0;sl<4;sl++) hv[sl]=g_slots_n[(b*8+s0+sl)*128+c];
    __syncthreads();
    #pragma unroll
    for(int sl=0;sl<4;sl++){
        TsP[c*8+s0+sl]=(a[sl]-CBs[s0+sl])*CSs[s0+sl];
        HsP[c*8+s0+sl]=hv[sl];
    }
    __syncthreads();
    // updates = T @ Wv.T  (coalesced WvT, slot-pair fma2)
    {
        ull u0=0ull,u1=0ull;
        #pragma unroll 8
        for(int d=0;d<128;d++){
            float w=g_WvT[d*128+c]; ull wp=pk2(w,w);
            u0=fma2(wp,*(const ull*)(TsP+d*8+s0),u0);
            u1=fma2(wp,*(const ull*)(TsP+d*8+s0+2),u1);
        }
        float y0,y1,y2,y3; unpk(u0,y0,y1); unpk(u1,y2,y3);
        UsP[c*8+s0]=y0; UsP[c*8+s0+1]=y1; UsP[c*8+s0+2]=y2; UsP[c*8+s0+3]=y3;
    }
    __syncthreads();
    // GRU
    float sd[4];
    {
        ull xr[2]={0,0},xz[2]={0,0},xn[2]={0,0},hr[2]={0,0},hz[2]={0,0},hn[2]={0,0};
        #pragma unroll 4
        for(int d=0;d<128;d++){
            ull up0=*(const ull*)(UsP+d*8+s0), up1=*(const ull*)(UsP+d*8+s0+2);
            ull hp0=*(const ull*)(HsP+d*8+s0), hp1=*(const ull*)(HsP+d*8+s0+2);
            float w; ull wp;
            w=g_WihT[d*384+c];     wp=pk2(w,w); xr[0]=fma2(wp,up0,xr[0]); xr[1]=fma2(wp,up1,xr[1]);
            w=g_WihT[d*384+128+c]; wp=pk2(w,w); xz[0]=fma2(wp,up0,xz[0]); xz[1]=fma2(wp,up1,xz[1]);
            w=g_WihT[d*384+256+c]; wp=pk2(w,w); xn[0]=fma2(wp,up0,xn[0]); xn[1]=fma2(wp,up1,xn[1]);
            w=g_WhhT[d*384+c];     wp=pk2(w,w); hr[0]=fma2(wp,hp0,hr[0]); hr[1]=fma2(wp,hp1,hr[1]);
            w=g_WhhT[d*384+128+c]; wp=pk2(w,w); hz[0]=fma2(wp,hp0,hz[0]); hz[1]=fma2(wp,hp1,hz[1]);
            w=g_WhhT[d*384+256+c]; wp=pk2(w,w); hn[0]=fma2(wp,hp0,hn[0]); hn[1]=fma2(wp,hp1,hn[1]);
        }
        float XR[4],XZ[4],XN[4],HR[4],HZ[4],HN[4];
        unpk(xr[0],XR[0],XR[1]); unpk(xr[1],XR[2],XR[3]);
        unpk(xz[0],XZ[0],XZ[1]); unpk(xz[1],XZ[2],XZ[3]);
        unpk(xn[0],XN[0],XN[1]); unpk(xn[1],XN[2],XN[3]);
        unpk(hr[0],HR[0],HR[1]); unpk(hr[1],HR[2],HR[3]);
        unpk(hz[0],HZ[0],HZ[1]); unpk(hz[1],HZ[2],HZ[3]);
        unpk(hn[0],HN[0],HN[1]); unpk(hn[1],HN[2],HN[3]);
        float bir=b_ih[c], biz=b_ih[128+c], bin=b_ih[256+c];
        float bhr=b_hh[c], bhz=b_hh[128+c], bhn=b_hh[256+c];
        #pragma unroll
        for(int sl=0;sl<4;sl++){
            float rr=1.f/(1.f+__expf(-(XR[sl]+bir+HR[sl]+bhr)));
            float zz=1.f/(1.f+__expf(-(XZ[sl]+biz+HZ[sl]+bhz)));
            float nn=tanhf(XN[sl]+bin+rr*(HN[sl]+bhn));
            sd[sl]=(1.f-zz)*nn+zz*hv[sl];
        }
    }
    // LN(sd) for MLP
    #pragma unroll
    for(int sl=0;sl<4;sl++){
        float m=gsum4w(sd[sl],t,red)*(1.f/128.f);
        float dv=sd[sl]-m;
        float var=gsum4w(dv*dv,t,red)*(1.f/128.f);
        LNP[c*8+s0+sl]=dv*rsqrtf(var+LN_EPS);
    }
    __syncthreads();
    // H1 = relu(LN @ W1.T + b1): thread owns hidden cols {2c, 2c+1}
    {
        ull A[4]={0,0,0,0};
        #pragma unroll 4
        for(int d=0;d<128;d++){
            ull w=*(const ull*)(g_W1T+d*256+2*c);
            #pragma unroll
            for(int sl=0;sl<4;sl++){
                float x=LNP[d*8+s0+sl];
                A[sl]=fma2(w,pk2(x,x),A[sl]);
            }
        }
        float bb0=b1[2*c], bb1=b1[2*c+1];
        #pragma unroll
        for(int sl=0;sl<4;sl++){
            float y0,y1; unpk(A[sl],y0,y1);
            H1P[(2*c)*8+s0+sl]  =fmaxf(y0+bb0,0.f);
            H1P[(2*c+1)*8+s0+sl]=fmaxf(y1+bb1,0.f);
        }
    }
    __syncthreads();
    // o = sd + H1 @ W2.T + b2
    float o[4];
    {
        ull O0=0ull,O1=0ull;
        #pragma unroll 8
        for(int h=0;h<256;h++){
            float w=g_W2T[h*128+c]; ull wp=pk2(w,w);
            O0=fma2(wp,*(const ull*)(H1P+h*8+s0),O0);
            O1=fma2(wp,*(const ull*)(H1P+h*8+s0+2),O1);
        }
        float y0,y1,y2,y3; unpk(O0,y0,y1); unpk(O1,y2,y3);
        float bb=b2[c];
        o[0]=sd[0]+bb+y0; o[1]=sd[1]+bb+y1; o[2]=sd[2]+bb+y2; o[3]=sd[3]+bb+y3;
    }
    #pragma unroll
    for(int sl=0;sl<4;sl++) out[(b*8+s0+sl)*128+c]=o[sl];
    __syncthreads();
    if(!last) project4(b,t,c,g2,o,LNP,QsP,red,Wk);   // LNP reused as SNP
}

extern "C" void kernel_launch(void* const* d_in, const int* in_sizes, int n_in,
                              void* d_out, int out_size){
    const float* inputs=(const float*)d_in[0];
    const float* noise =(const float*)d_in[1];
    const float* smu   =(const float*)d_in[2];
    const float* sls   =(const float*)d_in[3];
    const float* Wq    =(const float*)d_in[4];
    const float* Wk    =(const float*)d_in[5];
    const float* Wv    =(const float*)d_in[6];
    const float* W_ih  =(const float*)d_in[7];
    const float* W_hh  =(const float*)d_in[8];
    const float* b_ih  =(const float*)d_in[9];
    const float* b_hh  =(const float*)d_in[10];
    const float* W1    =(const float*)d_in[11];
    const float* b1    =(const float*)d_in[12];
    const float* W2    =(const float*)d_in[13];
    const float* b2    =(const float*)d_in[14];
    float* out=(float*)d_out;

    cudaFuncSetAttribute(k_attn, cudaFuncAttributeMaxDynamicSharedMemorySize, ATTN_SMEM_BYTES);

    k_transpose<<<768,256>>>(W_ih,W_hh,W1,W2,Wv,Wq);
    k_init_proj<<<128,256>>>(noise,smu,sls,Wk);
    for(int it=0; it<3; it++){
        dim3 g(64,128);
        k_attn<<<g,256,ATTN_SMEM_BYTES>>>(inputs);
        k_update<<<128,256>>>(Wk,b_ih,b_hh,b1,b2,out, it==2);
    }
}

// round 15
// speedup vs baseline: 1.0565x; 1.0565x over previous
#include <cuda_runtime.h>
#include <cstdint>

#define LN_EPS 1e-5f
#define EPS_ATTN 1e-8f
#define SCALE 0.08838834764831845f
typedef unsigned long long ull;

__device__ __forceinline__ ull fma2(ull a, ull b, ull c){ ull d; asm("fma.rn.f32x2 %0,%1,%2,%3;":"=l"(d):"l"(a),"l"(b),"l"(c)); return d; }
__device__ __forceinline__ ull add2(ull a, ull b){ ull d; asm("add.rn.f32x2 %0,%1,%2;":"=l"(d):"l"(a),"l"(b)); return d; }
__device__ __forceinline__ ull pk2(float lo, float hi){ ull d; asm("mov.b64 %0,{%1,%2};":"=l"(d):"f"(lo),"f"(hi)); return d; }
__device__ __forceinline__ void unpk(ull v, float&lo, float&hi){ asm("mov.b64 {%0,%1},%2;":"=f"(lo),"=f"(hi):"l"(v)); }
__device__ __forceinline__ float up2(ull v){ float a,b; unpk(v,a,b); return a+b; }

__device__ float g_slots_n[131072];
__device__ float g_qk[131072];
__device__ float g_qksum[1024];
__device__ float g_part[8388608];   // [b][64 tiles][8 s][128]
__device__ float g_cs[65536];
__device__ float g_cb[65536];
// packed weights
__device__ __align__(16) float g_Wg [131072]; // [128 d][128 c][8: ihr,ihz,ihn,hhr,hhz,hhn,0,0]
__device__ __align__(16) float g_W1T[32768];  // [128 d][256 j]
__device__ __align__(16) float g_W2P[32768];  // [128 h2][128 c][2: h=2h2, 2h2+1]
__device__ __align__(16) float g_WvT[16384];  // [128 d][128 c]
__device__ __align__(16) float g_WqT[16384];  // [128 d][128 c]

// ---- one-time weight packing ----
__global__ void k_transpose(const float* __restrict__ Wih, const float* __restrict__ Whh,
                            const float* __restrict__ W1, const float* __restrict__ W2,
                            const float* __restrict__ Wv, const float* __restrict__ Wq){
    int i = blockIdx.x*256 + threadIdx.x;
    if(i < 131072){
        int d=i>>10, rem=i&1023, c=rem>>3, k=rem&7;
        float v=0.f;
        if(k==0) v=Wih[(c    )*128+d];
        else if(k==1) v=Wih[(c+128)*128+d];
        else if(k==2) v=Wih[(c+256)*128+d];
        else if(k==3) v=Whh[(c    )*128+d];
        else if(k==4) v=Whh[(c+128)*128+d];
        else if(k==5) v=Whh[(c+256)*128+d];
        g_Wg[i]=v; return;
    }
    i -= 131072;
    if(i < 32768){ int d=i>>8, j=i&255; g_W1T[i]=W1[j*128+d]; return; }
    i -= 32768;
    if(i < 32768){ int h2=i>>8, rem=i&255, c=rem>>1, j=rem&1; g_W2P[i]=W2[c*256+2*h2+j]; return; }
    i -= 32768;
    if(i < 16384){ int d=i>>7, c=i&127; g_WvT[i]=Wv[c*128+d]; return; }
    i -= 16384;
    if(i < 16384){ int d=i>>7, c=i&127; g_WqT[i]=Wq[c*128+d]; }
}

// ---- 512-thread group sum: group = 128 threads (4 warps) ----
__device__ __forceinline__ float gsum(float v, int t, volatile float* red){
    #pragma unroll
    for(int o=16;o>0;o>>=1) v += __shfl_xor_sync(0xffffffffu,v,o);
    if((t&31)==0) red[t>>5]=v;
    __syncthreads();
    int base=(t>>7)<<2;
    v = red[base]+red[base+1]+red[base+2]+red[base+3];
    __syncthreads();
    return v;
}

// ---- projection for slot pair {2p, 2p+1}: LN -> slots_n, q=sn@Wq.T, qk=q@Wk ----
__device__ __forceinline__ void project2(int b, int t, int c, int p, const float* o,
    float* SNP, float* QsP, volatile float* red, const float* __restrict__ Wk)
{
    int s0=2*p;
    #pragma unroll
    for(int sl=0;sl<2;sl++){
        float m = gsum(o[sl],t,red)*(1.f/128.f);
        float dv = o[sl]-m;
        float var = gsum(dv*dv,t,red)*(1.f/128.f);
        float sn = dv*rsqrtf(var+LN_EPS);
        SNP[c*8+s0+sl]=sn;
        g_slots_n[(b*8+s0+sl)*128+c]=sn;
    }
    __syncthreads();
    ull q=0ull;
    #pragma unroll 8
    for(int d=0;d<128;d++){
        float w=g_WqT[d*128+c];
        q=fma2(pk2(w,w),*(const ull*)(SNP+d*8+s0),q);
    }
    { float y0,y1; unpk(q,y0,y1); *(ull*)(QsP+c*8+s0)=pk2(y0,y1); }
    __syncthreads();
    ull k=0ull;
    #pragma unroll 8
    for(int d=0;d<128;d++){
        float w=Wk[d*128+c];
        k=fma2(pk2(w,w),*(const ull*)(QsP+d*8+s0),k);
    }
    float kk[2]; unpk(k,kk[0],kk[1]);
    #pragma unroll
    for(int sl=0;sl<2;sl++){
        g_qk[(b*8+s0+sl)*128+c]=kk[sl];
        float qs=gsum(kk[sl],t,red);
        if(c==0) g_qksum[b*8+s0+sl]=qs;
    }
}

__global__ void __launch_bounds__(512) k_init_proj(
    const float* __restrict__ noise, const float* __restrict__ mu, const float* __restrict__ ls,
    const float* __restrict__ Wk)
{
    __shared__ __align__(16) float SNP[1024];
    __shared__ __align__(16) float QsP[1024];
    __shared__ volatile float red[16];
    int b=blockIdx.x, t=threadIdx.x, c=t&127, p=t>>7, s0=2*p;
    float e=expf(ls[c]), m=mu[c];
    float sd[2];
    #pragma unroll
    for(int sl=0;sl<2;sl++)
        sd[sl]=m+e*noise[(b*8+s0+sl)*128+c];
    project2(b,t,c,p,sd,SNP,QsP,red,Wk);
}

// ---- attention: grid(64,128), 256 threads, 4 blocks/SM ----
__global__ void __launch_bounds__(256,4) k_attn(const float* __restrict__ inputs){
    __shared__ __align__(16) float XS[64*132];   // 8448
    __shared__ __align__(16) float QK[1024];
    __shared__ float LG[64*9];
    __shared__ __align__(8) float AA[512];
    __shared__ float QS[8], MUb[64], RSb[64], CW[16], CBv[16];
    const int t=threadIdx.x, lane=t&31, w=t>>5;
    const int tile=blockIdx.x, b=blockIdx.y;
    const int row=t&63, h=t>>6, sb=2*h;

    { const float4* gsrc=(const float4*)(inputs + ((size_t)b*4096 + tile*64)*128);
      #pragma unroll 8
      for(int j=t;j<2048;j+=256){ int r=j>>5,cc=j&31; *(float4*)(XS+r*132+cc*4)=gsrc[j]; } }
    { int s=t>>5, i=lane*4;
      *(float4*)(QK+s*128+i)=*(const float4*)(g_qk+(b*8+s)*128+i);
      if(t<8) QS[t]=g_qksum[b*8+t]; }
    __syncthreads();

    // phase 2: thread (h,row) computes 2 slot dots; h==0 also LN stats
    float at0, at1, mu, rstd;
    {
        ull p0=0ull,p1=0ull,s1=0ull,s2=0ull;
        const ulonglong2* xp=(const ulonglong2*)(XS+row*132);
        const ulonglong2* qa=(const ulonglong2*)(QK+sb*128);
        const ulonglong2* qb=(const ulonglong2*)(QK+(sb+1)*128);
        #pragma unroll 4
        for(int cc=0;cc<32;cc++){
            ulonglong2 xv=xp[cc];
            if(h==0){ s1=add2(s1,xv.x); s1=add2(s1,xv.y);
                      s2=fma2(xv.x,xv.x,s2); s2=fma2(xv.y,xv.y,s2); }
            ulonglong2 qv=qa[cc]; p0=fma2(xv.x,qv.x,p0); p0=fma2(xv.y,qv.y,p0);
            qv=qb[cc]; p1=fma2(xv.x,qv.x,p1); p1=fma2(xv.y,qv.y,p1);
        }
        LG[row*9+sb]=up2(p0); LG[row*9+sb+1]=up2(p1);
        if(h==0){
            float sum=up2(s1), ssq=up2(s2);
            float m_=sum*(1.f/128.f);
            MUb[row]=m_;
            RSb[row]=rsqrtf(ssq*(1.f/128.f)-m_*m_+LN_EPS);
        }
    }
    __syncthreads();
    mu=MUb[row]; rstd=RSb[row];
    {
        float lg[8];
        #pragma unroll
        for(int k=0;k<8;k++) lg[k]=SCALE*rstd*(LG[row*9+k]-mu*QS[k]);
        float m=lg[0];
        #pragma unroll
        for(int k=1;k<8;k++) m=fmaxf(m,lg[k]);
        float e[8], tot=0.f;
        #pragma unroll
        for(int k=0;k<8;k++){ e[k]=__expf(lg[k]-m); tot+=e[k]; }
        float inv=1.f/tot;
        at0=e[sb]*inv+EPS_ATTN;
        at1=e[sb+1]*inv+EPS_ATTN;
        AA[row*8+sb]=at0*rstd;
        AA[row*8+sb+1]=at1*rstd;
    }
    {
        float v0=at0, v1=at1, u0=at0*rstd*mu, u1=at1*rstd*mu;
        #pragma unroll
        for(int o=16;o>0;o>>=1){
            v0+=__shfl_xor_sync(0xffffffffu,v0,o);
            v1+=__shfl_xor_sync(0xffffffffu,v1,o);
            u0+=__shfl_xor_sync(0xffffffffu,u0,o);
            u1+=__shfl_xor_sync(0xffffffffu,u1,o);
        }
        if(lane==0){ CW[w*2]=v0; CW[w*2+1]=v1; CBv[w*2]=u0; CBv[w*2+1]=u1; }
    }
    __syncthreads();

    // phase 3: warp w accumulates slot s=w over all 64 rows; lane owns 4 cols
    {
        ull a0=0ull, a1=0ull;
        #pragma unroll 4
        for(int r=0;r<64;r++){
            ulonglong2 xv=*(const ulonglong2*)(XS + r*132 + lane*4);
            float av=AA[r*8+w];
            ull ap=pk2(av,av);
            a0=fma2(ap,xv.x,a0); a1=fma2(ap,xv.y,a1);
        }
        *(ulonglong2*)(g_part+((size_t)(b*64+tile)*8+w)*128+lane*4)=make_ulonglong2(a0,a1);
    }
    if(t<8){
        int s=t, hh=s>>1, j=s&1;
        g_cs[(b*64+tile)*8+s]=CW[(2*hh)*2+j]+CW[(2*hh+1)*2+j];
        g_cb[(b*64+tile)*8+s]=CBv[(2*hh)*2+j]+CBv[(2*hh+1)*2+j];
    }
}

// ---- fused update + projection: 128 blocks x 512 threads ----
__global__ void __launch_bounds__(512) k_update(
    const float* __restrict__ Wk,
    const float* __restrict__ b_ih, const float* __restrict__ b_hh,
    const float* __restrict__ b1, const float* __restrict__ b2,
    float* __restrict__ out, int last)
{
    __shared__ __align__(16) float TsP[1024];
    __shared__ __align__(16) float UsP[1024];
    __shared__ __align__(16) float HsP[1024];
    __shared__ __align__(16) float LNP[1024];
    __shared__ __align__(16) float QsP[1024];
    __shared__ __align__(16) float H1P[2048];
    __shared__ float CSs[8], CBs[8];
    __shared__ volatile float red[16];
    int b=blockIdx.x, t=threadIdx.x, c=t&127, p=t>>7, s0=2*p;

    if(t<8){
        float cs=0.f,cb=0.f;
        #pragma unroll 8
        for(int k=0;k<64;k++){ cs+=g_cs[(b*64+k)*8+t]; cb+=g_cb[(b*64+k)*8+t]; }
        CSs[t]=1.f/cs; CBs[t]=cb;
    }
    float a0=0.f, a1=0.f;
    {
        const float* pp=g_part+(size_t)(b*64)*1024 + s0*128 + c;
        #pragma unroll 8
        for(int k=0;k<64;k++){ a0+=pp[(size_t)k*1024]; a1+=pp[(size_t)k*1024+128]; }
    }
    float hv0=g_slots_n[(b*8+s0)*128+c];
    float hv1=g_slots_n[(b*8+s0+1)*128+c];
    __syncthreads();
    TsP[c*8+s0]  =(a0-CBs[s0])  *CSs[s0];
    TsP[c*8+s0+1]=(a1-CBs[s0+1])*CSs[s0+1];
    *(ull*)(HsP+c*8+s0)=pk2(hv0,hv1);
    __syncthreads();
    // updates = T @ Wv.T
    {
        ull u=0ull;
        #pragma unroll 8
        for(int d=0;d<128;d++){
            float w=g_WvT[d*128+c];
            u=fma2(pk2(w,w),*(const ull*)(TsP+d*8+s0),u);
        }
        *(ull*)(UsP+c*8+s0)=u;
    }
    __syncthreads();
    // GRU: packed gate weights, 2 LDG.128 per d
    float sd[2];
    {
        ull xr=0,xz=0,xn=0,hr=0,hz=0,hn=0;
        #pragma unroll 4
        for(int d=0;d<128;d++){
            float4 wa=*(const float4*)(g_Wg + (size_t)d*1024 + c*8);
            float4 wb=*(const float4*)(g_Wg + (size_t)d*1024 + c*8 + 4);
            ull uv=*(const ull*)(UsP + d*8 + s0);
            ull hvv=*(const ull*)(HsP + d*8 + s0);
            xr=fma2(pk2(wa.x,wa.x),uv,xr);
            xz=fma2(pk2(wa.y,wa.y),uv,xz);
            xn=fma2(pk2(wa.z,wa.z),uv,xn);
            hr=fma2(pk2(wa.w,wa.w),hvv,hr);
            hz=fma2(pk2(wb.x,wb.x),hvv,hz);
            hn=fma2(pk2(wb.y,wb.y),hvv,hn);
        }
        float XR[2],XZ[2],XN[2],HR[2],HZ[2],HN[2];
        unpk(xr,XR[0],XR[1]); unpk(xz,XZ[0],XZ[1]); unpk(xn,XN[0],XN[1]);
        unpk(hr,HR[0],HR[1]); unpk(hz,HZ[0],HZ[1]); unpk(hn,HN[0],HN[1]);
        float bir=b_ih[c], biz=b_ih[128+c], bin=b_ih[256+c];
        float bhr=b_hh[c], bhz=b_hh[128+c], bhn=b_hh[256+c];
        float hvv[2]={hv0,hv1};
        #pragma unroll
        for(int sl=0;sl<2;sl++){
            float rr=1.f/(1.f+__expf(-(XR[sl]+bir+HR[sl]+bhr)));
            float zz=1.f/(1.f+__expf(-(XZ[sl]+biz+HZ[sl]+bhz)));
            float nn=tanhf(XN[sl]+bin+rr*(HN[sl]+bhn));
            sd[sl]=(1.f-zz)*nn+zz*hvv[sl];
        }
    }
    // LN(sd) for MLP
    #pragma unroll
    for(int sl=0;sl<2;sl++){
        float m=gsum(sd[sl],t,red)*(1.f/128.f);
        float dv=sd[sl]-m;
        float var=gsum(dv*dv,t,red)*(1.f/128.f);
        LNP[c*8+s0+sl]=dv*rsqrtf(var+LN_EPS);
    }
    __syncthreads();
    // H1 = relu(LN @ W1.T + b1): thread owns hidden cols {2c, 2c+1}
    {
        ull A0=0ull, A1=0ull;
        #pragma unroll 4
        for(int d=0;d<128;d++){
            ull w01=*(const ull*)(g_W1T + d*256 + 2*c);
            float x0,x1; unpk(*(const ull*)(LNP+d*8+s0),x0,x1);
            A0=fma2(w01,pk2(x0,x0),A0);
            A1=fma2(w01,pk2(x1,x1),A1);
        }
        float h00,h10,h01,h11;
        unpk(A0,h00,h10); unpk(A1,h01,h11);
        float bb0=b1[2*c], bb1=b1[2*c+1];
        *(ull*)(H1P+(2*c)*8+s0)  =pk2(fmaxf(h00+bb0,0.f), fmaxf(h01+bb0,0.f));
        *(ull*)(H1P+(2*c+1)*8+s0)=pk2(fmaxf(h10+bb1,0.f), fmaxf(h11+bb1,0.f));
    }
    __syncthreads();
    // o = sd + H1 @ W2.T + b2  (W2 packed in h-pairs)
    float o[2];
    {
        ull O=0ull;
        #pragma unroll 8
        for(int h2=0;h2<128;h2++){
            float2 w=*(const float2*)(g_W2P + h2*256 + c*2);
            O=fma2(pk2(w.x,w.x),*(const ull*)(H1P+(2*h2  )*8+s0),O);
            O=fma2(pk2(w.y,w.y),*(const ull*)(H1P+(2*h2+1)*8+s0),O);
        }
        float y0,y1; unpk(O,y0,y1);
        float bb=b2[c];
        o[0]=sd[0]+bb+y0; o[1]=sd[1]+bb+y1;
    }
    out[(b*8+s0  )*128+c]=o[0];
    out[(b*8+s0+1)*128+c]=o[1];
    __syncthreads();
    if(!last) project2(b,t,c,p,o,LNP,QsP,red,Wk);   // LNP reused as SNP
}

extern "C" void kernel_launch(void* const* d_in, const int* in_sizes, int n_in,
                              void* d_out, int out_size){
    const float* inputs=(const float*)d_in[0];
    const float* noise =(const float*)d_in[1];
    const float* smu   =(const float*)d_in[2];
    const float* sls   =(const float*)d_in[3];
    const float* Wq    =(const float*)d_in[4];
    const float* Wk    =(const float*)d_in[5];
    const float* Wv    =(const float*)d_in[6];
    const float* W_ih  =(const float*)d_in[7];
    const float* W_hh  =(const float*)d_in[8];
    const float* b_ih  =(const float*)d_in[9];
    const float* b_hh  =(const float*)d_in[10];
    const float* W1    =(const float*)d_in[11];
    const float* b1    =(const float*)d_in[12];
    const float* W2    =(const float*)d_in[13];
    const float* b2    =(const float*)d_in[14];
    float* out=(float*)d_out;

    k_transpose<<<896,256>>>(W_ih,W_hh,W1,W2,Wv,Wq);
    k_init_proj<<<128,512>>>(noise,smu,sls,Wk);
    for(int it=0; it<3; it++){
        dim3 g(64,128);
        k_attn<<<g,256>>>(inputs);
        k_update<<<128,512>>>(Wk,b_ih,b_hh,b1,b2,out, it==2);
    }
}

// round 16
// speedup vs baseline: 1.4738x; 1.3949x over previous
#include <cuda_runtime.h>
#include <cstdint>

#define LN_EPS 1e-5f
#define EPS_ATTN 1e-8f
#define SCALE 0.08838834764831845f
typedef unsigned long long ull;

__device__ __forceinline__ ull fma2(ull a, ull b, ull c){ ull d; asm("fma.rn.f32x2 %0,%1,%2,%3;":"=l"(d):"l"(a),"l"(b),"l"(c)); return d; }
__device__ __forceinline__ ull add2(ull a, ull b){ ull d; asm("add.rn.f32x2 %0,%1,%2;":"=l"(d):"l"(a),"l"(b)); return d; }
__device__ __forceinline__ ull pk2(float lo, float hi){ ull d; asm("mov.b64 %0,{%1,%2};":"=l"(d):"f"(lo),"f"(hi)); return d; }
__device__ __forceinline__ void unpk(ull v, float&lo, float&hi){ asm("mov.b64 {%0,%1},%2;":"=f"(lo),"=f"(hi):"l"(v)); }
__device__ __forceinline__ float up2(ull v){ float a,b; unpk(v,a,b); return a+b; }

__device__ float g_slots_n[131072];
__device__ float g_qk[131072];
__device__ float g_qksum[1024];
__device__ float g_part[8388608];   // [b][64 tiles][8 s][128]
__device__ float g_cs[65536];
__device__ float g_cb[65536];
// packed weights
__device__ __align__(16) float g_Wg [131072]; // [128 d][128 c][8: ihr,ihz,ihn,hhr,hhz,hhn,0,0]
__device__ __align__(16) float g_W1T[32768];  // [128 d][256 j]
__device__ __align__(16) float g_W2P[32768];  // [128 h2][128 c][2]
__device__ __align__(16) float g_WvT[16384];  // [128 d][128 c]
__device__ __align__(16) float g_WqT[16384];  // [128 d][128 c]

__global__ void k_transpose(const float* __restrict__ Wih, const float* __restrict__ Whh,
                            const float* __restrict__ W1, const float* __restrict__ W2,
                            const float* __restrict__ Wv, const float* __restrict__ Wq){
    int i = blockIdx.x*256 + threadIdx.x;
    if(i < 131072){
        int d=i>>10, rem=i&1023, c=rem>>3, k=rem&7;
        float v=0.f;
        if(k==0) v=Wih[(c    )*128+d];
        else if(k==1) v=Wih[(c+128)*128+d];
        else if(k==2) v=Wih[(c+256)*128+d];
        else if(k==3) v=Whh[(c    )*128+d];
        else if(k==4) v=Whh[(c+128)*128+d];
        else if(k==5) v=Whh[(c+256)*128+d];
        g_Wg[i]=v; return;
    }
    i -= 131072;
    if(i < 32768){ int d=i>>8, j=i&255; g_W1T[i]=W1[j*128+d]; return; }
    i -= 32768;
    if(i < 32768){ int h2=i>>8, rem=i&255, c=rem>>1, j=rem&1; g_W2P[i]=W2[c*256+2*h2+j]; return; }
    i -= 32768;
    if(i < 16384){ int d=i>>7, c=i&127; g_WvT[i]=Wv[c*128+d]; return; }
    i -= 16384;
    if(i < 16384){ int d=i>>7, c=i&127; g_WqT[i]=Wq[c*128+d]; }
}

// group sum over 128-thread group q=t>>7 (4 warps); red must hold 4*numgroups
__device__ __forceinline__ float gsum(float v, int t, volatile float* red){
    #pragma unroll
    for(int o=16;o>0;o>>=1) v += __shfl_xor_sync(0xffffffffu,v,o);
    if((t&31)==0) red[t>>5]=v;
    __syncthreads();
    int base=(t>>7)<<2;
    v = red[base]+red[base+1]+red[base+2]+red[base+3];
    __syncthreads();
    return v;
}

// ---- 512-thread init projection (once) ----
__device__ __forceinline__ void project2(int b, int t, int c, int p, const float* o,
    float* SNP, float* QsP, volatile float* red, const float* __restrict__ Wk)
{
    int s0=2*p;
    #pragma unroll
    for(int sl=0;sl<2;sl++){
        float m = gsum(o[sl],t,red)*(1.f/128.f);
        float dv = o[sl]-m;
        float var = gsum(dv*dv,t,red)*(1.f/128.f);
        float sn = dv*rsqrtf(var+LN_EPS);
        SNP[c*8+s0+sl]=sn;
        g_slots_n[(b*8+s0+sl)*128+c]=sn;
    }
    __syncthreads();
    ull q=0ull;
    #pragma unroll 8
    for(int d=0;d<128;d++){
        float w=g_WqT[d*128+c];
        q=fma2(pk2(w,w),*(const ull*)(SNP+d*8+s0),q);
    }
    { float y0,y1; unpk(q,y0,y1); *(ull*)(QsP+c*8+s0)=pk2(y0,y1); }
    __syncthreads();
    ull k=0ull;
    #pragma unroll 8
    for(int d=0;d<128;d++){
        float w=Wk[d*128+c];
        k=fma2(pk2(w,w),*(const ull*)(QsP+d*8+s0),k);
    }
    float kk[2]; unpk(k,kk[0],kk[1]);
    #pragma unroll
    for(int sl=0;sl<2;sl++){
        g_qk[(b*8+s0+sl)*128+c]=kk[sl];
        float qs=gsum(kk[sl],t,red);
        if(c==0) g_qksum[b*8+s0+sl]=qs;
    }
}

__global__ void __launch_bounds__(512) k_init_proj(
    const float* __restrict__ noise, const float* __restrict__ mu, const float* __restrict__ ls,
    const float* __restrict__ Wk)
{
    __shared__ __align__(16) float SNP[1024];
    __shared__ __align__(16) float QsP[1024];
    __shared__ volatile float red[16];
    int b=blockIdx.x, t=threadIdx.x, c=t&127, p=t>>7, s0=2*p;
    float e=expf(ls[c]), m=mu[c];
    float sd[2];
    #pragma unroll
    for(int sl=0;sl<2;sl++)
        sd[sl]=m+e*noise[(b*8+s0+sl)*128+c];
    project2(b,t,c,p,sd,SNP,QsP,red,Wk);
}

// ---- attention: grid(64,128), 256 threads, 4 blocks/SM ----
__global__ void __launch_bounds__(256,4) k_attn(const float* __restrict__ inputs){
    __shared__ __align__(16) float XS[64*132];   // 8448
    __shared__ __align__(16) float U[2048];      // QK/LG/QS/MUb/RSb (phase2) | PART (phase3)
    __shared__ __align__(16) float AA[512];
    __shared__ float CW[16], CBv[16];
    float* QK  = U;          // 1024
    float* LG  = U + 1024;   // 576
    float* QS  = U + 1600;   // 8
    float* MUb = U + 1608;   // 64
    float* RSb = U + 1672;   // 64
    float* PART= U;          // 2048 (phase3, after sync)
    const int t=threadIdx.x, lane=t&31, w=t>>5;
    const int tile=blockIdx.x, b=blockIdx.y;
    const int row=t&63, h=t>>6, sb=2*h;

    { const float4* gsrc=(const float4*)(inputs + ((size_t)b*4096 + tile*64)*128);
      #pragma unroll 8
      for(int j=t;j<2048;j+=256){ int r=j>>5,cc=j&31; *(float4*)(XS+r*132+cc*4)=gsrc[j]; } }
    { int s=t>>5, i=lane*4;
      *(float4*)(QK+s*128+i)=*(const float4*)(g_qk+(b*8+s)*128+i);
      if(t<8) QS[t]=g_qksum[b*8+t]; }
    __syncthreads();

    // phase 2: thread (h,row): dots for slots {2h,2h+1}; h==0 also LN stats
    float at0, at1, mu, rstd;
    {
        ull p0=0ull,p1=0ull,s1=0ull,s2=0ull;
        const ulonglong2* xp=(const ulonglong2*)(XS+row*132);
        const ulonglong2* qa=(const ulonglong2*)(QK+sb*128);
        const ulonglong2* qb=(const ulonglong2*)(QK+(sb+1)*128);
        #pragma unroll 4
        for(int cc=0;cc<32;cc++){
            ulonglong2 xv=xp[cc];
            if(h==0){ s1=add2(s1,xv.x); s1=add2(s1,xv.y);
                      s2=fma2(xv.x,xv.x,s2); s2=fma2(xv.y,xv.y,s2); }
            ulonglong2 qv=qa[cc]; p0=fma2(xv.x,qv.x,p0); p0=fma2(xv.y,qv.y,p0);
            qv=qb[cc]; p1=fma2(xv.x,qv.x,p1); p1=fma2(xv.y,qv.y,p1);
        }
        LG[row*9+sb]=up2(p0); LG[row*9+sb+1]=up2(p1);
        if(h==0){
            float sum=up2(s1), ssq=up2(s2);
            float m_=sum*(1.f/128.f);
            MUb[row]=m_;
            RSb[row]=rsqrtf(ssq*(1.f/128.f)-m_*m_+LN_EPS);
        }
    }
    __syncthreads();
    mu=MUb[row]; rstd=RSb[row];
    {
        float lg[8];
        #pragma unroll
        for(int k=0;k<8;k++) lg[k]=SCALE*rstd*(LG[row*9+k]-mu*QS[k]);
        float m=lg[0];
        #pragma unroll
        for(int k=1;k<8;k++) m=fmaxf(m,lg[k]);
        float e[8], tot=0.f;
        #pragma unroll
        for(int k=0;k<8;k++){ e[k]=__expf(lg[k]-m); tot+=e[k]; }
        float inv=1.f/tot;
        at0=e[sb]*inv+EPS_ATTN;
        at1=e[sb+1]*inv+EPS_ATTN;
        AA[row*8+sb]=at0*rstd;
        AA[row*8+sb+1]=at1*rstd;
    }
    {
        float v0=at0, v1=at1, u0=at0*rstd*mu, u1=at1*rstd*mu;
        #pragma unroll
        for(int o=16;o>0;o>>=1){
            v0+=__shfl_xor_sync(0xffffffffu,v0,o);
            v1+=__shfl_xor_sync(0xffffffffu,v1,o);
            u0+=__shfl_xor_sync(0xffffffffu,u0,o);
            u1+=__shfl_xor_sync(0xffffffffu,u1,o);
        }
        if(lane==0){ CW[w*2]=v0; CW[w*2+1]=v1; CBv[w*2]=u0; CBv[w*2+1]=u1; }
    }
    __syncthreads();   // QK/LG/QS/MUb/RSb now dead -> U becomes PART

    // phase 3: warp task (sq=slot quad, rh=row half, ch=col half); lane owns 2 cols
    {
        const int sq=w&1, rh=(w>>1)&1, ch=w>>2;
        ull a4[4]={0ull,0ull,0ull,0ull};
        #pragma unroll 4
        for(int r0=0;r0<32;r0++){
            int r=rh*32+r0;
            ull xv=*(const ull*)(XS + r*132 + ch*64 + lane*2);
            float4 av=*(const float4*)(AA + r*8 + sq*4);
            a4[0]=fma2(pk2(av.x,av.x),xv,a4[0]);
            a4[1]=fma2(pk2(av.y,av.y),xv,a4[1]);
            a4[2]=fma2(pk2(av.z,av.z),xv,a4[2]);
            a4[3]=fma2(pk2(av.w,av.w),xv,a4[3]);
        }
        #pragma unroll
        for(int sl=0;sl<4;sl++)
            *(ull*)(PART + ((sq*2+rh)*4+sl)*128 + ch*64 + lane*2) = a4[sl];
    }
    if(t<8){
        int s=t, hh=s>>1, j=s&1;
        g_cs[(b*64+tile)*8+s]=CW[(2*hh)*2+j]+CW[(2*hh+1)*2+j];
        g_cb[(b*64+tile)*8+s]=CBv[(2*hh)*2+j]+CBv[(2*hh+1)*2+j];
    }
    __syncthreads();
    {
        int s=t>>5, c0=lane*4;
        int sq2=s>>2, sl=s&3;
        float o[4];
        #pragma unroll
        for(int j=0;j<4;j++){
            int c=c0+j;
            o[j]=PART[((sq2*2+0)*4+sl)*128+c] + PART[((sq2*2+1)*4+sl)*128+c];
        }
        *(float4*)(g_part+((size_t)(b*64+tile)*8+s)*128+c0)=make_float4(o[0],o[1],o[2],o[3]);
    }
}

// ---- fused update+projection: 128 blocks x 1024 threads ----
// thread = (c = t&127, q = t>>7) with dh=q&1 (d-half), p=q>>1 (slot pair s0=2p)
#define UPD_SMEM_FLOATS 13360
__global__ void __launch_bounds__(1024,1) k_update(
    const float* __restrict__ Wk,
    const float* __restrict__ b_ih, const float* __restrict__ b_hh,
    const float* __restrict__ b1, const float* __restrict__ b2,
    float* __restrict__ out, int last)
{
    extern __shared__ float smem[];
    float* TsP = smem;            // 1024
    float* UsP = smem + 1024;     // 1024
    float* HsP = smem + 2048;     // 1024
    float* LNP = smem + 3072;     // 1024 (reused as SNP in projection)
    float* QsP = smem + 4096;     // 1024
    float* H1P = smem + 5120;     // 2048
    ull*  RedU = (ull*)(smem + 7168);   // 3072 ull
    float* CSs = smem + 13312;    // 8
    float* CBs = smem + 13320;    // 8
    volatile float* red = smem + 13328; // 32

    int b=blockIdx.x, t=threadIdx.x;
    int c=t&127, q=t>>7, dh=q&1, p=q>>1, s0=2*p;
    int i512=p*128+c;

    // phase A: colsum/csub + part-sum (k split across dh)
    if(t<8){
        float cs=0.f,cb=0.f;
        #pragma unroll 8
        for(int k=0;k<64;k++){ cs+=g_cs[(b*64+k)*8+t]; cb+=g_cb[(b*64+k)*8+t]; }
        CSs[t]=1.f/cs; CBs[t]=cb;
    }
    float a0=0.f, a1=0.f;
    {
        const float* pp=g_part+(size_t)b*65536 + s0*128 + c;
        #pragma unroll 8
        for(int k=dh*32;k<dh*32+32;k++){ a0+=pp[(size_t)k*1024]; a1+=pp[(size_t)k*1024+128]; }
    }
    float hv0=0.f, hv1=0.f;
    if(dh==0){
        hv0=g_slots_n[(b*8+s0)*128+c];
        hv1=g_slots_n[(b*8+s0+1)*128+c];
    }
    if(dh==1) RedU[i512]=pk2(a0,a1);
    __syncthreads();
    if(dh==0){
        float x0,x1; unpk(RedU[i512],x0,x1);
        a0+=x0; a1+=x1;
        TsP[c*8+s0]  =(a0-CBs[s0])  *CSs[s0];
        TsP[c*8+s0+1]=(a1-CBs[s0+1])*CSs[s0+1];
        *(ull*)(HsP+c*8+s0)=pk2(hv0,hv1);
    }
    __syncthreads();

    // phase B: updates = T @ Wv.T (d split)
    {
        ull u=0ull;
        #pragma unroll 8
        for(int d=dh*64;d<dh*64+64;d++){
            float w=g_WvT[d*128+c];
            u=fma2(pk2(w,w),*(const ull*)(TsP+d*8+s0),u);
        }
        if(dh==1) RedU[i512]=u;
        __syncthreads();
        if(dh==0){ u=add2(u,RedU[i512]); *(ull*)(UsP+c*8+s0)=u; }
        __syncthreads();
    }

    // phase C: GRU (d split, 6 packed gate accumulators)
    float sd[2]={0.f,0.f};
    {
        ull g6[6]={0ull,0ull,0ull,0ull,0ull,0ull};
        #pragma unroll 4
        for(int d=dh*64;d<dh*64+64;d++){
            float4 wa=*(const float4*)(g_Wg + (size_t)d*1024 + c*8);
            float4 wb=*(const float4*)(g_Wg + (size_t)d*1024 + c*8 + 4);
            ull uv=*(const ull*)(UsP + d*8 + s0);
            ull hvv=*(const ull*)(HsP + d*8 + s0);
            g6[0]=fma2(pk2(wa.x,wa.x),uv,g6[0]);
            g6[1]=fma2(pk2(wa.y,wa.y),uv,g6[1]);
            g6[2]=fma2(pk2(wa.z,wa.z),uv,g6[2]);
            g6[3]=fma2(pk2(wa.w,wa.w),hvv,g6[3]);
            g6[4]=fma2(pk2(wb.x,wb.x),hvv,g6[4]);
            g6[5]=fma2(pk2(wb.y,wb.y),hvv,g6[5]);
        }
        if(dh==1){
            #pragma unroll
            for(int g=0;g<6;g++) RedU[i512*6+g]=g6[g];
        }
        __syncthreads();
        if(dh==0){
            #pragma unroll
            for(int g=0;g<6;g++) g6[g]=add2(g6[g],RedU[i512*6+g]);
            float XR[2],XZ[2],XN[2],HR[2],HZ[2],HN[2];
            unpk(g6[0],XR[0],XR[1]); unpk(g6[1],XZ[0],XZ[1]); unpk(g6[2],XN[0],XN[1]);
            unpk(g6[3],HR[0],HR[1]); unpk(g6[4],HZ[0],HZ[1]); unpk(g6[5],HN[0],HN[1]);
            float bir=b_ih[c], biz=b_ih[128+c], bin=b_ih[256+c];
            float bhr=b_hh[c], bhz=b_hh[128+c], bhn=b_hh[256+c];
            float hvv[2]={hv0,hv1};
            #pragma unroll
            for(int sl=0;sl<2;sl++){
                float rr=1.f/(1.f+__expf(-(XR[sl]+bir+HR[sl]+bhr)));
                float zz=1.f/(1.f+__expf(-(XZ[sl]+biz+HZ[sl]+bhz)));
                float nn=tanhf(XN[sl]+bin+rr*(HN[sl]+bhn));
                sd[sl]=(1.f-zz)*nn+zz*hvv[sl];
            }
        }
        __syncthreads();
    }

    // LN(sd) for MLP (all threads participate in gsum barriers)
    #pragma unroll
    for(int sl=0;sl<2;sl++){
        float m=gsum(sd[sl],t,red)*(1.f/128.f);
        float dv=sd[sl]-m;
        float var=gsum(dv*dv,t,red)*(1.f/128.f);
        if(dh==0) LNP[c*8+s0+sl]=dv*rsqrtf(var+LN_EPS);
    }
    __syncthreads();

    // phase D: H1 = relu(LN @ W1.T + b1) (d split; thread owns hidden {2c,2c+1})
    {
        ull A0=0ull, A1=0ull;
        #pragma unroll 4
        for(int d=dh*64;d<dh*64+64;d++){
            ull w01=*(const ull*)(g_W1T + d*256 + 2*c);
            float x0,x1; unpk(*(const ull*)(LNP+d*8+s0),x0,x1);
            A0=fma2(w01,pk2(x0,x0),A0);
            A1=fma2(w01,pk2(x1,x1),A1);
        }
        if(dh==1){ RedU[i512*2]=A0; RedU[i512*2+1]=A1; }
        __syncthreads();
        if(dh==0){
            A0=add2(A0,RedU[i512*2]); A1=add2(A1,RedU[i512*2+1]);
            float h00,h10,h01,h11;
            unpk(A0,h00,h10); unpk(A1,h01,h11);
            float bb0=b1[2*c], bb1=b1[2*c+1];
            *(ull*)(H1P+(2*c)*8+s0)  =pk2(fmaxf(h00+bb0,0.f), fmaxf(h01+bb0,0.f));
            *(ull*)(H1P+(2*c+1)*8+s0)=pk2(fmaxf(h10+bb1,0.f), fmaxf(h11+bb1,0.f));
        }
        __syncthreads();
    }

    // phase E: o = sd + H1 @ W2.T + b2 (h2 split)
    float o[2]={0.f,0.f};
    {
        ull O=0ull;
        #pragma unroll 8
        for(int h2=dh*64;h2<dh*64+64;h2++){
            float2 w=*(const float2*)(g_W2P + h2*256 + c*2);
            O=fma2(pk2(w.x,w.x),*(const ull*)(H1P+(2*h2  )*8+s0),O);
            O=fma2(pk2(w.y,w.y),*(const ull*)(H1P+(2*h2+1)*8+s0),O);
        }
        if(dh==1) RedU[i512]=O;
        __syncthreads();
        if(dh==0){
            O=add2(O,RedU[i512]);
            float y0,y1; unpk(O,y0,y1);
            float bb=b2[c];
            o[0]=sd[0]+bb+y0; o[1]=sd[1]+bb+y1;
            out[(b*8+s0  )*128+c]=o[0];
            out[(b*8+s0+1)*128+c]=o[1];
        }
        __syncthreads();
    }

    if(!last){
        // projection: LN(o) -> SNP(=LNP), q=sn@Wq.T, qk=q@Wk, qksum  (d split)
        float sn[2];
        #pragma unroll
        for(int sl=0;sl<2;sl++){
            float m=gsum(o[sl],t,red)*(1.f/128.f);
            float dv=o[sl]-m;
            float var=gsum(dv*dv,t,red)*(1.f/128.f);
            sn[sl]=dv*rsqrtf(var+LN_EPS);
        }
        if(dh==0){
            LNP[c*8+s0]=sn[0]; LNP[c*8+s0+1]=sn[1];
            g_slots_n[(b*8+s0  )*128+c]=sn[0];
            g_slots_n[(b*8+s0+1)*128+c]=sn[1];
        }
        __syncthreads();
        ull qa=0ull;
        #pragma unroll 8
        for(int d=dh*64;d<dh*64+64;d++){
            float w=g_WqT[d*128+c];
            qa=fma2(pk2(w,w),*(const ull*)(LNP+d*8+s0),qa);
        }
        if(dh==1) RedU[i512]=qa;
        __syncthreads();
        if(dh==0){ qa=add2(qa,RedU[i512]); *(ull*)(QsP+c*8+s0)=qa; }
        __syncthreads();
        ull ka=0ull;
        #pragma unroll 8
        for(int d=dh*64;d<dh*64+64;d++){
            float w=Wk[d*128+c];
            ka=fma2(pk2(w,w),*(const ull*)(QsP+d*8+s0),ka);
        }
        if(dh==1) RedU[i512]=ka;
        __syncthreads();
        float kk0=0.f, kk1=0.f;
        if(dh==0){ ka=add2(ka,RedU[i512]); unpk(ka,kk0,kk1); }
        float qs0=gsum(kk0,t,red);
        float qs1=gsum(kk1,t,red);
        if(dh==0){
            g_qk[(b*8+s0  )*128+c]=kk0;
            g_qk[(b*8+s0+1)*128+c]=kk1;
            if(c==0){ g_qksum[b*8+s0]=qs0; g_qksum[b*8+s0+1]=qs1; }
        }
    }
}

extern "C" void kernel_launch(void* const* d_in, const int* in_sizes, int n_in,
                              void* d_out, int out_size){
    const float* inputs=(const float*)d_in[0];
    const float* noise =(const float*)d_in[1];
    const float* smu   =(const float*)d_in[2];
    const float* sls   =(const float*)d_in[3];
    const float* Wq    =(const float*)d_in[4];
    const float* Wk    =(const float*)d_in[5];
    const float* Wv    =(const float*)d_in[6];
    const float* W_ih  =(const float*)d_in[7];
    const float* W_hh  =(const float*)d_in[8];
    const float* b_ih  =(const float*)d_in[9];
    const float* b_hh  =(const float*)d_in[10];
    const float* W1    =(const float*)d_in[11];
    const float* b1    =(const float*)d_in[12];
    const float* W2    =(const float*)d_in[13];
    const float* b2    =(const float*)d_in[14];
    float* out=(float*)d_out;

    cudaFuncSetAttribute(k_update, cudaFuncAttributeMaxDynamicSharedMemorySize,
                         UPD_SMEM_FLOATS*4);

    k_transpose<<<896,256>>>(W_ih,W_hh,W1,W2,Wv,Wq);
    k_init_proj<<<128,512>>>(noise,smu,sls,Wk);
    for(int it=0; it<3; it++){
        dim3 g(64,128);
        k_attn<<<g,256>>>(inputs);
        k_update<<<128,1024,UPD_SMEM_FLOATS*4>>>(Wk,b_ih,b_hh,b1,b2,out, it==2);
    }
}